// round 10
// baseline (speedup 1.0000x reference)
#include <cuda_runtime.h>
#include <cuda_bf16.h>
#include <math.h>
#include <stdint.h>

#define TB 512

#define Bn   1024
#define DIMn 384
#define HIDn 64
#define Gn   48
#define MIDn 128

// ---------------- Shared-memory byte map ----------------
#define HS_STRIDE 272
#define HWB   104448
#define ZB    104448
#define Z_STRIDE 528
#define Z_BUFSZ 16896

#define S_PG  50688
#define S_X   52992
#define S_INV 53376
#define S_SW  53760
#define S_SC  53824
#define S_RW  54208
#define S_DB  54256
#define S_UB  54384
#define S_PG2 54448
#define SMEM_FLOATS 56752   // 227008 bytes

// ---------------- mma.sync / ldmatrix helpers ----------------
__device__ __forceinline__ uint32_t smem_u32(const void* p) {
    uint32_t a;
    asm("{ .reg .u64 t; cvta.to.shared.u64 t, %1; cvt.u32.u64 %0, t; }" : "=r"(a) : "l"(p));
    return a;
}
__device__ __forceinline__ void mma_bf16(float* d, const uint32_t* a, const uint32_t* b) {
    asm volatile("mma.sync.aligned.m16n8k16.row.col.f32.bf16.bf16.f32 "
        "{%0,%1,%2,%3}, {%4,%5,%6,%7}, {%8,%9}, {%0,%1,%2,%3};"
        : "+f"(d[0]), "+f"(d[1]), "+f"(d[2]), "+f"(d[3])
        : "r"(a[0]), "r"(a[1]), "r"(a[2]), "r"(a[3]), "r"(b[0]), "r"(b[1]));
}
__device__ __forceinline__ void ldsm_x4(uint32_t* r, uint32_t addr) {
    asm volatile("ldmatrix.sync.aligned.m8n8.x4.shared.b16 {%0,%1,%2,%3}, [%4];"
        : "=r"(r[0]), "=r"(r[1]), "=r"(r[2]), "=r"(r[3]) : "r"(addr));
}

__device__ __forceinline__ float leaky(float v) { return (v >= 0.0f) ? v : 0.01f * v; }
__device__ __forceinline__ float gelu_exact(float v) {
    return 0.5f * v * (1.0f + erff(v * 0.70710678118654752f));
}
__device__ __forceinline__ uint32_t bf2(float a, float b) {
    __nv_bfloat162 t; t.x = __float2bfloat16(a); t.y = __float2bfloat16(b);
    return *reinterpret_cast<uint32_t*>(&t);
}
__device__ __forceinline__ void split2(float a, float b, uint32_t &hi, uint32_t &lo) {
    __nv_bfloat16 ha = __float2bfloat16(a);
    __nv_bfloat16 hb = __float2bfloat16(b);
    __nv_bfloat162 hp; hp.x = ha; hp.y = hb;
    hi = *reinterpret_cast<uint32_t*>(&hp);
    lo = bf2(a - __bfloat162float(ha), b - __bfloat162float(hb));
}
__device__ __forceinline__ uint32_t hs_addr(int i, int w) {
    int s = (i >> 3) & 7;
    return (uint32_t)(i * HS_STRIDE + ((((w >> 2) ^ s) << 4) | ((w & 3) << 2)));
}

__global__ void __launch_bounds__(TB, 1) autoreg_fused_kernel(
    const float* __restrict__ x,
    const float* __restrict__ W,
    const float* __restrict__ bia,
    const float* __restrict__ patchw,
    const float* __restrict__ pw1,
    const float* __restrict__ pb1,
    const float* __restrict__ pw2,
    const float* __restrict__ pb2,
    const float* __restrict__ projw,
    const float* __restrict__ projb,
    const float* __restrict__ dw,
    const float* __restrict__ db,
    const float* __restrict__ uw,
    const float* __restrict__ ub,
    float* __restrict__ out)
{
    extern __shared__ float sm[];
    char* smb = (char*)sm;
    const int tid  = threadIdx.x;
    const int wid  = tid >> 5;
    const int lid  = tid & 31;
    const int bidx = blockIdx.x;
    const uint32_t smem_base = smem_u32(sm);

    // ---- Load x row, bias vectors, raw patch weights ----
    for (int i = tid; i < DIMn; i += TB) {
        float xv = x[bidx * DIMn + i];
        sm[S_X + i]   = xv;
        sm[S_INV + i] = 1.0f / (fabsf(xv) + 1e-6f);
    }
    if (tid < MIDn) sm[S_DB + tid] = db[tid];
    if (tid >= 128 && tid < 192) sm[S_UB + tid - 128] = ub[tid - 128];
    if (tid >= 192 && tid < 256) sm[S_SW + tid - 192] = patchw[tid - 192];
    __syncthreads();

    // ---- Patch-weight softmax (thread 0; overlaps stage A) ----
    if (tid == 0) {
        float m = -1e30f;
        for (int i = 0; i < 64; i++) m = fmaxf(m, sm[S_SW + i]);
        float s = 0.0f;
        for (int i = 0; i < 64; i++) { float e = expf(sm[S_SW + i] - m); sm[S_SW + i] = e; s += e; }
        float is = 1.0f / s;
        for (int i = 0; i < 64; i++) sm[S_SW + i] *= is;
    }

    // ---- Stage A: H = gelu(x*W + inv*b), bf16 hi/lo split, float4 loads ----
    for (int t = tid; t < 6144; t += TB) {
        int i = t >> 4, w4 = t & 15;
        float4 Wv = *(const float4*)(W + i * 64 + 4 * w4);
        float4 Bv = *(const float4*)(bia + i * 64 + 4 * w4);
        float xv = sm[S_X + i], iv = sm[S_INV + i];
        float v0 = gelu_exact(xv * Wv.x + iv * Bv.x);
        float v1 = gelu_exact(xv * Wv.y + iv * Bv.y);
        float v2 = gelu_exact(xv * Wv.z + iv * Bv.z);
        float v3 = gelu_exact(xv * Wv.w + iv * Bv.w);
        uint32_t h0, l0, h1, l1;
        split2(v0, v1, h0, l0);
        split2(v2, v3, h1, l1);
        uint32_t a = hs_addr(i, 2 * w4);
        *(uint2*)(smb + a)       = make_uint2(h0, h1);
        *(uint2*)(smb + a + 128) = make_uint2(l0, l1);
    }
    __syncthreads();

    // ---- Stage B: Hw ----
    for (int t = tid; t < 1536; t += TB) {
        int h = t >> 5, w = t & 31;
        float v0[8], v1[8];
        #pragma unroll
        for (int l = 0; l < 8; l++) {
            uint32_t a = hs_addr(h * 8 + l, w);
            uint32_t hw_ = *(uint32_t*)(smb + a);
            uint32_t lw_ = *(uint32_t*)(smb + a + 128);
            __nv_bfloat162 hb = *(__nv_bfloat162*)&hw_;
            __nv_bfloat162 lb = *(__nv_bfloat162*)&lw_;
            v0[l] = __bfloat162float(hb.x) + __bfloat162float(lb.x);
            v1[l] = __bfloat162float(hb.y) + __bfloat162float(lb.y);
        }
        int sh = h & 7;
        #pragma unroll
        for (int k = 0; k < 8; k++) {
            float a0 = 0.0f, a1 = 0.0f;
            #pragma unroll
            for (int l = 0; l < 8; l++) {
                float wv = sm[S_SW + k * 8 + l];
                a0 = fmaf(wv, v0[l], a0);
                a1 = fmaf(wv, v1[l], a1);
            }
            uint32_t hw2, lw2; split2(a0, a1, hw2, lw2);
            int W2 = k * 32 + w;
            uint32_t off = HWB + h * 2048 + ((((W2 >> 2) ^ sh) << 4) | ((W2 & 3) << 2));
            *(uint32_t*)(smb + off)        = hw2;
            *(uint32_t*)(smb + off + 1024) = lw2;
        }
    }
    __syncthreads();

    // ---- Gather loop-invariant weight B fragments ----
    // Producers (0-7): n16 strip of dw (32 regs). Consumers (8-15): n16 strip of uw + m-split (64 regs).
    const int eg = wid >> 3;
    const int sn = wid & 7;             // producer strip
    const int sn2 = wid & 3;            // consumer strip
    const int m2c = (wid >> 2) & 1;     // consumer m-half
    const int bq = lid >> 2;
    const int bk = 2 * (lid & 3);

    uint32_t bWh[32], bWl[32];
    if (eg == 0) {
        #pragma unroll
        for (int j = 0; j < 2; j++)
            #pragma unroll
            for (int s = 0; s < 4; s++)
                #pragma unroll
                for (int i = 0; i < 2; i++) {
                    const float* p = dw + (16 * sn + 8 * j + bq) * 64 + 16 * s + 8 * i + bk;
                    split2(p[0], p[1], bWh[(j * 4 + s) * 2 + i], bWl[(j * 4 + s) * 2 + i]);
                }
    } else {
        #pragma unroll
        for (int j = 0; j < 2; j++)
            #pragma unroll
            for (int s = 0; s < 8; s++)
                #pragma unroll
                for (int i = 0; i < 2; i++) {
                    const float* p = uw + (16 * sn2 + 8 * j + bq) * 128 + 16 * s + 8 * i + bk;
                    split2(p[0], p[1], bWh[(j * 8 + s) * 2 + i], bWl[(j * 8 + s) * 2 + i]);
                }
    }

    // ---- Stage C (tensor, warps 0-11, K-split): Pg partials = H(48x512) @ Hw^T ----
    const int arow  = lid & 15;
    const int ahalf = lid >> 4;
    if (wid < 12) {
        const int mtc = wid >> 2;       // m16 tile 0..2
        const int sub = wid & 3;
        const int nh  = sub >> 1;       // n24 half
        const int kk  = sub & 1;        // K half (s 0-15 / 16-31)
        float acc[3][4];
        #pragma unroll
        for (int j = 0; j < 3; j++)
            #pragma unroll
            for (int q = 0; q < 4; q++) acc[j][q] = 0.0f;

        #pragma unroll 4
        for (int s0 = 0; s0 < 16; s0++) {
            int s = kk * 16 + s0;
            int i = (16 * mtc + arow) * 8 + (s >> 2);
            int colA = ((s & 3) * 2 + ahalf) ^ ((i >> 3) & 7);
            uint32_t aaddr = smem_base + i * HS_STRIDE + (colA << 4);
            uint32_t ah[4], al[4];
            ldsm_x4(ah, aaddr);
            ldsm_x4(al, aaddr + 128);
            #pragma unroll
            for (int j = 0; j < 3; j++) {
                int hrow = 24 * nh + 8 * j + (lid & 7);
                int colB = (2 * s + ((lid >> 3) & 1)) ^ (hrow & 7);
                uint32_t baddr = smem_base + HWB + hrow * 2048 +
                                 ((lid >= 16) ? 1024 : 0) + (colB << 4);
                uint32_t bb[4];
                ldsm_x4(bb, baddr);
                mma_bf16(acc[j], ah, bb);
                mma_bf16(acc[j], ah, bb + 2);
                mma_bf16(acc[j], al, bb);
            }
        }
        float* pg = kk ? &sm[S_PG2] : &sm[S_PG];
        #pragma unroll
        for (int j = 0; j < 3; j++) {
            int r = 16 * mtc + (lid >> 2);
            int c = 24 * nh + 8 * j + 2 * (lid & 3);
            *(float2*)&pg[r * 48 + c]       = make_float2(acc[j][0], acc[j][1]);
            *(float2*)&pg[(r + 8) * 48 + c] = make_float2(acc[j][2], acc[j][3]);
        }
    }
    __syncthreads();

    // ---- Stage D: sum K-partials + elementwise affines + leaky ----
    for (int t = tid; t < Gn * Gn; t += TB) {
        float v = sm[S_PG + t] + sm[S_PG2 + t];
        v = leaky(fmaf(v, pw1[t], pb1[t]));
        v = leaky(fmaf(v, pw2[t], pb2[t]));
        sm[S_PG + t] = v;
    }
    __syncthreads();

    // ---- Row softmax + row_weights (4 lanes per row) ----
    if (tid < 192) {
        int r = tid >> 2, q = tid & 3;
        const float* row = &sm[S_PG + r * 48 + q * 12];
        float m = -1e30f;
        #pragma unroll
        for (int h2 = 0; h2 < 12; h2++) m = fmaxf(m, row[h2]);
        m = fmaxf(m, __shfl_xor_sync(0xFFFFFFFF, m, 1));
        m = fmaxf(m, __shfl_xor_sync(0xFFFFFFFF, m, 2));
        float s = 0.0f;
        #pragma unroll
        for (int h2 = 0; h2 < 12; h2++) s += expf(row[h2] - m);
        s += __shfl_xor_sync(0xFFFFFFFF, s, 1);
        s += __shfl_xor_sync(0xFFFFFFFF, s, 2);
        float inv_s = 1.0f / s;
        float rw = 0.0f;
        #pragma unroll
        for (int h2 = 0; h2 < 12; h2++) {
            float p = expf(row[h2] - m) * inv_s;
            rw += 1.0f / (1.0f + p * p);
        }
        rw += __shfl_xor_sync(0xFFFFFFFF, rw, 1);
        rw += __shfl_xor_sync(0xFFFFFFFF, rw, 2);
        if (q == 0) sm[S_RW + r] = rw;
    }
    __syncthreads();

    // ---- scales ----
    if (tid < DIMn) {
        float acc = projb[tid];
        const float* pr = &projw[tid * Gn];
        #pragma unroll
        for (int g = 0; g < Gn; g++) acc = fmaf(sm[S_RW + g], pr[g], acc);
        sm[S_SC + tid] = acc;
    }
    __syncthreads();   // scales visible; Hw region free for z buffers

    // ---- Stage E: warp-specialized pipeline, 12 chunks of 32 rows ----
    // Producers (0-7): n16 strip, both m16 halves, 4 chains.
    // Consumers (8-15): (m-half, n16 strip), 4 chains (s-parity).
    for (int it = 0; it <= 12; it++) {
        if (eg == 0 && it < 12) {
            const int ch = it;
            const uint32_t zbB = ZB + (ch & 1) * Z_BUFSZ;

            float d[2][2][4];
            #pragma unroll
            for (int m2 = 0; m2 < 2; m2++)
                #pragma unroll
                for (int j = 0; j < 2; j++)
                    #pragma unroll
                    for (int q = 0; q < 4; q++) d[m2][j][q] = 0.0f;

            #pragma unroll
            for (int s = 0; s < 4; s++) {
                #pragma unroll
                for (int m2 = 0; m2 < 2; m2++) {
                    int i = ch * 32 + m2 * 16 + arow;
                    int colA = (2 * s + ahalf) ^ ((i >> 3) & 7);
                    uint32_t aaddr = smem_base + i * HS_STRIDE + (colA << 4);
                    uint32_t ah[4], al[4];
                    ldsm_x4(ah, aaddr);
                    ldsm_x4(al, aaddr + 128);
                    #pragma unroll
                    for (int j = 0; j < 2; j++) {
                        mma_bf16(d[m2][j], ah, &bWh[(j * 4 + s) * 2]);
                        mma_bf16(d[m2][j], ah, &bWl[(j * 4 + s) * 2]);
                        mma_bf16(d[m2][j], al, &bWh[(j * 4 + s) * 2]);
                    }
                }
            }

            #pragma unroll
            for (int m2 = 0; m2 < 2; m2++) {
                const int zr = m2 * 16 + bq;
                const float s0 = sm[S_SC + ch * 32 + zr];
                const float s1 = sm[S_SC + ch * 32 + zr + 8];
                #pragma unroll
                for (int j = 0; j < 2; j++) {
                    int n0 = 16 * sn + 8 * j + bk;
                    float v0 = leaky(fmaf(d[m2][j][0], s0, sm[S_DB + n0]));
                    float v1 = leaky(fmaf(d[m2][j][1], s0, sm[S_DB + n0 + 1]));
                    uint32_t h, l; split2(v0, v1, h, l);
                    *(uint32_t*)(smb + zbB + zr * Z_STRIDE + n0 * 2)       = h;
                    *(uint32_t*)(smb + zbB + zr * Z_STRIDE + 256 + n0 * 2) = l;
                    v0 = leaky(fmaf(d[m2][j][2], s1, sm[S_DB + n0]));
                    v1 = leaky(fmaf(d[m2][j][3], s1, sm[S_DB + n0 + 1]));
                    split2(v0, v1, h, l);
                    *(uint32_t*)(smb + zbB + (zr + 8) * Z_STRIDE + n0 * 2)       = h;
                    *(uint32_t*)(smb + zbB + (zr + 8) * Z_STRIDE + 256 + n0 * 2) = l;
                }
            }
        }
        if (eg == 1 && it >= 1) {
            const int ch = it - 1;
            const uint32_t zbS = smem_base + ZB + (ch & 1) * Z_BUFSZ;

            float e[2][4], f[2][4];
            #pragma unroll
            for (int j = 0; j < 2; j++)
                #pragma unroll
                for (int q = 0; q < 4; q++) { e[j][q] = 0.0f; f[j][q] = 0.0f; }

            #pragma unroll
            for (int s = 0; s < 8; s++) {
                uint32_t ah[4], al[4];
                uint32_t za = zbS + (m2c * 16 + arow) * Z_STRIDE + 32 * s + ahalf * 16;
                ldsm_x4(ah, za);
                ldsm_x4(al, za + 256);
                #pragma unroll
                for (int j = 0; j < 2; j++) {
                    float* acc = (s & 1) ? f[j] : e[j];
                    mma_bf16(acc, ah, &bWh[(j * 8 + s) * 2]);
                    mma_bf16(acc, ah, &bWl[(j * 8 + s) * 2]);
                    mma_bf16(acc, al, &bWh[(j * 8 + s) * 2]);
                }
            }

            #pragma unroll
            for (int j = 0; j < 2; j++) {
                int n0 = 16 * sn2 + 8 * j + bk;
                int r  = ch * 32 + m2c * 16 + bq;
                float2 o;
                o.x = leaky(e[j][0] + f[j][0] + sm[S_UB + n0]);
                o.y = leaky(e[j][1] + f[j][1] + sm[S_UB + n0 + 1]);
                *(float2*)(out + ((size_t)(bidx * DIMn + r)) * 64 + n0) = o;
                o.x = leaky(e[j][2] + f[j][2] + sm[S_UB + n0]);
                o.y = leaky(e[j][3] + f[j][3] + sm[S_UB + n0 + 1]);
                *(float2*)(out + ((size_t)(bidx * DIMn + r + 8)) * 64 + n0) = o;
            }
        }
        __syncthreads();
    }
}

extern "C" void kernel_launch(void* const* d_in, const int* in_sizes, int n_in,
                              void* d_out, int out_size) {
    (void)in_sizes; (void)n_in; (void)out_size;
    const float* x      = (const float*)d_in[0];
    const float* W      = (const float*)d_in[1];
    const float* bia    = (const float*)d_in[2];
    const float* patchw = (const float*)d_in[3];
    const float* pw1    = (const float*)d_in[4];
    const float* pb1    = (const float*)d_in[5];
    const float* pw2    = (const float*)d_in[6];
    const float* pb2    = (const float*)d_in[7];
    const float* projw  = (const float*)d_in[8];
    const float* projb  = (const float*)d_in[9];
    const float* dw     = (const float*)d_in[10];
    const float* db     = (const float*)d_in[11];
    const float* uw     = (const float*)d_in[12];
    const float* ub     = (const float*)d_in[13];
    float* out = (float*)d_out;

    cudaFuncSetAttribute(autoreg_fused_kernel,
                         cudaFuncAttributeMaxDynamicSharedMemorySize,
                         SMEM_FLOATS * sizeof(float));
    autoreg_fused_kernel<<<Bn, TB, SMEM_FLOATS * sizeof(float)>>>(
        x, W, bia, patchw, pw1, pb1, pw2, pb2, projw, projb, dw, db, uw, ub, out);
}

// round 12
// speedup vs baseline: 1.4433x; 1.4433x over previous
#include <cuda_runtime.h>
#include <cuda_bf16.h>
#include <math.h>
#include <stdint.h>

#define TB 512

#define Bn   1024
#define DIMn 384
#define HIDn 64
#define Gn   48
#define MIDn 128

// ---------------- Shared-memory byte map ----------------
#define HS_STRIDE 272
#define HWB   104448
#define ZB    104448
#define Z_STRIDE 528
#define Z_BUFSZ 16896

#define S_PG  50688
#define S_X   52992
#define S_INV 53376
#define S_SW  53760
#define S_SC  53824
#define S_RW  54208
#define S_DB  54256
#define S_UB  54384
#define S_PG2 54448
#define SMEM_FLOATS 56752   // 227008 bytes

// ---------------- mma.sync / ldmatrix helpers ----------------
__device__ __forceinline__ uint32_t smem_u32(const void* p) {
    uint32_t a;
    asm("{ .reg .u64 t; cvta.to.shared.u64 t, %1; cvt.u32.u64 %0, t; }" : "=r"(a) : "l"(p));
    return a;
}
__device__ __forceinline__ void mma_bf16(float* d, const uint32_t* a, const uint32_t* b) {
    asm volatile("mma.sync.aligned.m16n8k16.row.col.f32.bf16.bf16.f32 "
        "{%0,%1,%2,%3}, {%4,%5,%6,%7}, {%8,%9}, {%0,%1,%2,%3};"
        : "+f"(d[0]), "+f"(d[1]), "+f"(d[2]), "+f"(d[3])
        : "r"(a[0]), "r"(a[1]), "r"(a[2]), "r"(a[3]), "r"(b[0]), "r"(b[1]));
}
__device__ __forceinline__ void ldsm_x4(uint32_t* r, uint32_t addr) {
    asm volatile("ldmatrix.sync.aligned.m8n8.x4.shared.b16 {%0,%1,%2,%3}, [%4];"
        : "=r"(r[0]), "=r"(r[1]), "=r"(r[2]), "=r"(r[3]) : "r"(addr));
}

__device__ __forceinline__ float leaky(float v) { return (v >= 0.0f) ? v : 0.01f * v; }
__device__ __forceinline__ float gelu_exact(float v) {
    return 0.5f * v * (1.0f + erff(v * 0.70710678118654752f));
}
__device__ __forceinline__ uint32_t bf2(float a, float b) {
    __nv_bfloat162 t; t.x = __float2bfloat16(a); t.y = __float2bfloat16(b);
    return *reinterpret_cast<uint32_t*>(&t);
}
__device__ __forceinline__ void split2(float a, float b, uint32_t &hi, uint32_t &lo) {
    __nv_bfloat16 ha = __float2bfloat16(a);
    __nv_bfloat16 hb = __float2bfloat16(b);
    __nv_bfloat162 hp; hp.x = ha; hp.y = hb;
    hi = *reinterpret_cast<uint32_t*>(&hp);
    lo = bf2(a - __bfloat162float(ha), b - __bfloat162float(hb));
}
__device__ __forceinline__ uint32_t hs_addr(int i, int w) {
    int s = (i >> 3) & 7;
    return (uint32_t)(i * HS_STRIDE + ((((w >> 2) ^ s) << 4) | ((w & 3) << 2)));
}

__global__ void __launch_bounds__(TB, 1) autoreg_fused_kernel(
    const float* __restrict__ x,
    const float* __restrict__ W,
    const float* __restrict__ bia,
    const float* __restrict__ patchw,
    const float* __restrict__ pw1,
    const float* __restrict__ pb1,
    const float* __restrict__ pw2,
    const float* __restrict__ pb2,
    const float* __restrict__ projw,
    const float* __restrict__ projb,
    const float* __restrict__ dw,
    const float* __restrict__ db,
    const float* __restrict__ uw,
    const float* __restrict__ ub,
    float* __restrict__ out)
{
    extern __shared__ float sm[];
    char* smb = (char*)sm;
    const int tid  = threadIdx.x;
    const int wid  = tid >> 5;
    const int lid  = tid & 31;
    const int bidx = blockIdx.x;
    const uint32_t smem_base = smem_u32(sm);

    // ---- Load x row, bias vectors, raw patch weights ----
    for (int i = tid; i < DIMn; i += TB) {
        float xv = x[bidx * DIMn + i];
        sm[S_X + i]   = xv;
        sm[S_INV + i] = 1.0f / (fabsf(xv) + 1e-6f);
    }
    if (tid < MIDn) sm[S_DB + tid] = db[tid];
    if (tid >= 128 && tid < 192) sm[S_UB + tid - 128] = ub[tid - 128];
    if (tid >= 192 && tid < 256) sm[S_SW + tid - 192] = patchw[tid - 192];
    __syncthreads();

    // ---- Patch-weight softmax (thread 0; overlaps stage A) ----
    if (tid == 0) {
        float m = -1e30f;
        for (int i = 0; i < 64; i++) m = fmaxf(m, sm[S_SW + i]);
        float s = 0.0f;
        for (int i = 0; i < 64; i++) { float e = expf(sm[S_SW + i] - m); sm[S_SW + i] = e; s += e; }
        float is = 1.0f / s;
        for (int i = 0; i < 64; i++) sm[S_SW + i] *= is;
    }

    // ---- Stage A: H = gelu(x*W + inv*b), bf16 hi/lo split, float4 loads ----
    for (int t = tid; t < 6144; t += TB) {
        int i = t >> 4, w4 = t & 15;
        float4 Wv = *(const float4*)(W + i * 64 + 4 * w4);
        float4 Bv = *(const float4*)(bia + i * 64 + 4 * w4);
        float xv = sm[S_X + i], iv = sm[S_INV + i];
        float v0 = gelu_exact(xv * Wv.x + iv * Bv.x);
        float v1 = gelu_exact(xv * Wv.y + iv * Bv.y);
        float v2 = gelu_exact(xv * Wv.z + iv * Bv.z);
        float v3 = gelu_exact(xv * Wv.w + iv * Bv.w);
        uint32_t h0, l0, h1, l1;
        split2(v0, v1, h0, l0);
        split2(v2, v3, h1, l1);
        uint32_t a = hs_addr(i, 2 * w4);
        *(uint2*)(smb + a)       = make_uint2(h0, h1);
        *(uint2*)(smb + a + 128) = make_uint2(l0, l1);
    }
    __syncthreads();

    // ---- Stage B: Hw ----
    for (int t = tid; t < 1536; t += TB) {
        int h = t >> 5, w = t & 31;
        float v0[8], v1[8];
        #pragma unroll
        for (int l = 0; l < 8; l++) {
            uint32_t a = hs_addr(h * 8 + l, w);
            uint32_t hw_ = *(uint32_t*)(smb + a);
            uint32_t lw_ = *(uint32_t*)(smb + a + 128);
            __nv_bfloat162 hb = *(__nv_bfloat162*)&hw_;
            __nv_bfloat162 lb = *(__nv_bfloat162*)&lw_;
            v0[l] = __bfloat162float(hb.x) + __bfloat162float(lb.x);
            v1[l] = __bfloat162float(hb.y) + __bfloat162float(lb.y);
        }
        int sh = h & 7;
        #pragma unroll
        for (int k = 0; k < 8; k++) {
            float a0 = 0.0f, a1 = 0.0f;
            #pragma unroll
            for (int l = 0; l < 8; l++) {
                float wv = sm[S_SW + k * 8 + l];
                a0 = fmaf(wv, v0[l], a0);
                a1 = fmaf(wv, v1[l], a1);
            }
            uint32_t hw2, lw2; split2(a0, a1, hw2, lw2);
            int W2 = k * 32 + w;
            uint32_t off = HWB + h * 2048 + ((((W2 >> 2) ^ sh) << 4) | ((W2 & 3) << 2));
            *(uint32_t*)(smb + off)        = hw2;
            *(uint32_t*)(smb + off + 1024) = lw2;
        }
    }
    __syncthreads();

    // ---- Gather loop-invariant weight B fragments (32 regs per warp, R9 layout) ----
    const int eg = wid >> 3;
    const int sn = wid & 7;
    const int bq = lid >> 2;
    const int bk = 2 * (lid & 3);

    uint32_t bWh[16], bWl[16];
    if (eg == 0) {
        #pragma unroll
        for (int j = 0; j < 2; j++)
            #pragma unroll
            for (int s = 0; s < 4; s++)
                #pragma unroll
                for (int i = 0; i < 2; i++) {
                    const float* p = dw + (16 * sn + 8 * j + bq) * 64 + 16 * s + 8 * i + bk;
                    split2(p[0], p[1], bWh[(j * 4 + s) * 2 + i], bWl[(j * 4 + s) * 2 + i]);
                }
    } else {
        #pragma unroll
        for (int s = 0; s < 8; s++)
            #pragma unroll
            for (int i = 0; i < 2; i++) {
                const float* p = uw + (8 * sn + bq) * 128 + 16 * s + 8 * i + bk;
                split2(p[0], p[1], bWh[s * 2 + i], bWl[s * 2 + i]);
            }
    }

    // ---- Stage C (tensor, warps 0-11, K-split): Pg partials = H(48x512) @ Hw^T ----
    const int arow  = lid & 15;
    const int ahalf = lid >> 4;
    if (wid < 12) {
        const int mtc = wid >> 2;       // m16 tile 0..2
        const int sub = wid & 3;
        const int nh  = sub >> 1;       // n24 half
        const int kk  = sub & 1;        // K half
        float acc[3][4];
        #pragma unroll
        for (int j = 0; j < 3; j++)
            #pragma unroll
            for (int q = 0; q < 4; q++) acc[j][q] = 0.0f;

        #pragma unroll 4
        for (int s0 = 0; s0 < 16; s0++) {
            int s = kk * 16 + s0;
            int i = (16 * mtc + arow) * 8 + (s >> 2);
            int colA = ((s & 3) * 2 + ahalf) ^ ((i >> 3) & 7);
            uint32_t aaddr = smem_base + i * HS_STRIDE + (colA << 4);
            uint32_t ah[4], al[4];
            ldsm_x4(ah, aaddr);
            ldsm_x4(al, aaddr + 128);
            #pragma unroll
            for (int j = 0; j < 3; j++) {
                int hrow = 24 * nh + 8 * j + (lid & 7);
                int colB = (2 * s + ((lid >> 3) & 1)) ^ (hrow & 7);
                uint32_t baddr = smem_base + HWB + hrow * 2048 +
                                 ((lid >= 16) ? 1024 : 0) + (colB << 4);
                uint32_t bb[4];
                ldsm_x4(bb, baddr);
                mma_bf16(acc[j], ah, bb);
                mma_bf16(acc[j], ah, bb + 2);
                mma_bf16(acc[j], al, bb);
            }
        }
        float* pg = kk ? &sm[S_PG2] : &sm[S_PG];
        #pragma unroll
        for (int j = 0; j < 3; j++) {
            int r = 16 * mtc + (lid >> 2);
            int c = 24 * nh + 8 * j + 2 * (lid & 3);
            *(float2*)&pg[r * 48 + c]       = make_float2(acc[j][0], acc[j][1]);
            *(float2*)&pg[(r + 8) * 48 + c] = make_float2(acc[j][2], acc[j][3]);
        }
    }
    __syncthreads();

    // ---- Stage D: sum K-partials + elementwise affines + leaky ----
    for (int t = tid; t < Gn * Gn; t += TB) {
        float v = sm[S_PG + t] + sm[S_PG2 + t];
        v = leaky(fmaf(v, pw1[t], pb1[t]));
        v = leaky(fmaf(v, pw2[t], pb2[t]));
        sm[S_PG + t] = v;
    }
    __syncthreads();

    // ---- Row softmax + row_weights (4 lanes per row) ----
    if (tid < 192) {
        int r = tid >> 2, q = tid & 3;
        const float* row = &sm[S_PG + r * 48 + q * 12];
        float m = -1e30f;
        #pragma unroll
        for (int h2 = 0; h2 < 12; h2++) m = fmaxf(m, row[h2]);
        m = fmaxf(m, __shfl_xor_sync(0xFFFFFFFF, m, 1));
        m = fmaxf(m, __shfl_xor_sync(0xFFFFFFFF, m, 2));
        float s = 0.0f;
        #pragma unroll
        for (int h2 = 0; h2 < 12; h2++) s += expf(row[h2] - m);
        s += __shfl_xor_sync(0xFFFFFFFF, s, 1);
        s += __shfl_xor_sync(0xFFFFFFFF, s, 2);
        float inv_s = 1.0f / s;
        float rw = 0.0f;
        #pragma unroll
        for (int h2 = 0; h2 < 12; h2++) {
            float p = expf(row[h2] - m) * inv_s;
            rw += 1.0f / (1.0f + p * p);
        }
        rw += __shfl_xor_sync(0xFFFFFFFF, rw, 1);
        rw += __shfl_xor_sync(0xFFFFFFFF, rw, 2);
        if (q == 0) sm[S_RW + r] = rw;
    }
    __syncthreads();

    // ---- scales ----
    if (tid < DIMn) {
        float acc = projb[tid];
        const float* pr = &projw[tid * Gn];
        #pragma unroll
        for (int g = 0; g < Gn; g++) acc = fmaf(sm[S_RW + g], pr[g], acc);
        sm[S_SC + tid] = acc;
    }
    __syncthreads();   // scales visible; Hw region free for z buffers

    // ---- Stage E: warp-specialized pipeline, 12 chunks of 32 rows (R9 layout) ----
    for (int it = 0; it <= 12; it++) {
        if (eg == 0 && it < 12) {
            const int ch = it;
            const uint32_t zbB = ZB + (ch & 1) * Z_BUFSZ;

            float d[2][2][4];
            #pragma unroll
            for (int m2 = 0; m2 < 2; m2++)
                #pragma unroll
                for (int j = 0; j < 2; j++)
                    #pragma unroll
                    for (int q = 0; q < 4; q++) d[m2][j][q] = 0.0f;

            #pragma unroll
            for (int s = 0; s < 4; s++) {
                #pragma unroll
                for (int m2 = 0; m2 < 2; m2++) {
                    int i = ch * 32 + m2 * 16 + arow;
                    int colA = (2 * s + ahalf) ^ ((i >> 3) & 7);
                    uint32_t aaddr = smem_base + i * HS_STRIDE + (colA << 4);
                    uint32_t ah[4], al[4];
                    ldsm_x4(ah, aaddr);
                    ldsm_x4(al, aaddr + 128);
                    #pragma unroll
                    for (int j = 0; j < 2; j++) {
                        mma_bf16(d[m2][j], ah, &bWh[(j * 4 + s) * 2]);
                        mma_bf16(d[m2][j], ah, &bWl[(j * 4 + s) * 2]);
                        mma_bf16(d[m2][j], al, &bWh[(j * 4 + s) * 2]);
                    }
                }
            }

            #pragma unroll
            for (int m2 = 0; m2 < 2; m2++) {
                const int zr = m2 * 16 + bq;
                const float s0 = sm[S_SC + ch * 32 + zr];
                const float s1 = sm[S_SC + ch * 32 + zr + 8];
                #pragma unroll
                for (int j = 0; j < 2; j++) {
                    int n0 = 16 * sn + 8 * j + bk;
                    float v0 = leaky(fmaf(d[m2][j][0], s0, sm[S_DB + n0]));
                    float v1 = leaky(fmaf(d[m2][j][1], s0, sm[S_DB + n0 + 1]));
                    uint32_t h, l; split2(v0, v1, h, l);
                    *(uint32_t*)(smb + zbB + zr * Z_STRIDE + n0 * 2)       = h;
                    *(uint32_t*)(smb + zbB + zr * Z_STRIDE + 256 + n0 * 2) = l;
                    v0 = leaky(fmaf(d[m2][j][2], s1, sm[S_DB + n0]));
                    v1 = leaky(fmaf(d[m2][j][3], s1, sm[S_DB + n0 + 1]));
                    split2(v0, v1, h, l);
                    *(uint32_t*)(smb + zbB + (zr + 8) * Z_STRIDE + n0 * 2)       = h;
                    *(uint32_t*)(smb + zbB + (zr + 8) * Z_STRIDE + 256 + n0 * 2) = l;
                }
            }
        }
        if (eg == 1 && it >= 1) {
            const int ch = it - 1;
            const uint32_t zbS = smem_base + ZB + (ch & 1) * Z_BUFSZ;

            float e[2][4], f[2][4];
            #pragma unroll
            for (int m2 = 0; m2 < 2; m2++)
                #pragma unroll
                for (int q = 0; q < 4; q++) { e[m2][q] = 0.0f; f[m2][q] = 0.0f; }

            #pragma unroll
            for (int s = 0; s < 8; s++) {
                #pragma unroll
                for (int m2 = 0; m2 < 2; m2++) {
                    uint32_t ah[4], al[4];
                    uint32_t za = zbS + (m2 * 16 + arow) * Z_STRIDE + 32 * s + ahalf * 16;
                    ldsm_x4(ah, za);
                    ldsm_x4(al, za + 256);
                    float* acc = (s & 1) ? f[m2] : e[m2];
                    mma_bf16(acc, ah, &bWh[s * 2]);
                    mma_bf16(acc, ah, &bWl[s * 2]);
                    mma_bf16(acc, al, &bWh[s * 2]);
                }
            }

            #pragma unroll
            for (int m2 = 0; m2 < 2; m2++) {
                const int R = ch * 32 + m2 * 16;
                int n0 = 8 * sn + bk;
                int r  = R + bq;
                float2 o;
                o.x = leaky(e[m2][0] + f[m2][0] + sm[S_UB + n0]);
                o.y = leaky(e[m2][1] + f[m2][1] + sm[S_UB + n0 + 1]);
                *(float2*)(out + ((size_t)(bidx * DIMn + r)) * 64 + n0) = o;
                o.x = leaky(e[m2][2] + f[m2][2] + sm[S_UB + n0]);
                o.y = leaky(e[m2][3] + f[m2][3] + sm[S_UB + n0 + 1]);
                *(float2*)(out + ((size_t)(bidx * DIMn + r + 8)) * 64 + n0) = o;
            }
        }
        __syncthreads();
    }
}

extern "C" void kernel_launch(void* const* d_in, const int* in_sizes, int n_in,
                              void* d_out, int out_size) {
    (void)in_sizes; (void)n_in; (void)out_size;
    const float* x      = (const float*)d_in[0];
    const float* W      = (const float*)d_in[1];
    const float* bia    = (const float*)d_in[2];
    const float* patchw = (const float*)d_in[3];
    const float* pw1    = (const float*)d_in[4];
    const float* pb1    = (const float*)d_in[5];
    const float* pw2    = (const float*)d_in[6];
    const float* pb2    = (const float*)d_in[7];
    const float* projw  = (const float*)d_in[8];
    const float* projb  = (const float*)d_in[9];
    const float* dw     = (const float*)d_in[10];
    const float* db     = (const float*)d_in[11];
    const float* uw     = (const float*)d_in[12];
    const float* ub     = (const float*)d_in[13];
    float* out = (float*)d_out;

    cudaFuncSetAttribute(autoreg_fused_kernel,
                         cudaFuncAttributeMaxDynamicSharedMemorySize,
                         SMEM_FLOATS * sizeof(float));
    autoreg_fused_kernel<<<Bn, TB, SMEM_FLOATS * sizeof(float)>>>(
        x, W, bia, patchw, pw1, pb1, pw2, pb2, projw, projb, dw, db, uw, ub, out);
}